// round 13
// baseline (speedup 1.0000x reference)
#include <cuda_runtime.h>
#include <cstdint>

#define BB 1024
#define TT 2048
#define FF 16
#define SS 300    // FORWARD_STEPS
#define BPB 4     // batch elements per block
#define GRID 256  // 1024/4; occ 2 -> 296 slots on 148 SMs >= 256, all co-resident
#define NT 320    // >= SS: one thread per step
#define ITERS 4   // ceil(BPB*SS / NT) = ceil(1200/320)

// Cross-block state, zeroed by a memset node before each kernel replay.
struct SyncState {
    unsigned mask[SS];   // 4-bit validity per step (bit j-1 = any temp_j != 0 over all b)
    unsigned arrive;     // grid-barrier arrival counter
};
__device__ SyncState g_state;

// ---------------------------------------------------------------------------
// Single persistent kernel, 256 blocks x 320 threads, 2 CTAs/SM (20 warps/SM
// for staging latency hiding; R12 showed 1 CTA/SM = 10 warps is the limiter).
// Block k owns batches [k*4, k*4+4). Thread t (< 300) owns step t.
//
// Phase 1 front-batches ALL staging loads (two aligned float2s per row,
// f10..f11 and f12..f13 — same 32B DRAM sectors as float4s but half the
// register payload, so the full MLP stays in flight without spill).
// Phase 2 computes y_j (exact _rn order) while loads fly; phase 3 drains to
// smem. Gather stays register-resident across a 256-arrival spin barrier;
// <=1 atomicOr per (block, step).
//
// Bit-exactness: identical _rn op sequences; y_j >= 0 -> SS-1 clamp == TT-1
// clamp (rel_err 0.0 on every passing round since R2).
// ---------------------------------------------------------------------------
__global__ void __launch_bounds__(NT, 2)
k_all(const float* __restrict__ x, const float* __restrict__ wp,
      float* __restrict__ out) {
    const int tid = threadIdx.x;
    const int b0  = blockIdx.x * BPB;

    __shared__ float s_feat[BPB][SS][5];  // features 10..13 (+pad; 5 coprime 32 banks)
    __shared__ float s_y[BPB][4];

    // ---- phase 1: front-batch ALL staging loads into registers (MLP~8) ----
    float2 p[ITERS], q[ITERS];
#pragma unroll
    for (int k = 0; k < ITERS; k++) {
        int i = tid + k * NT;
        if (i < BPB * SS) {
            int bl = i / SS, r = i - bl * SS;
            const float* base = x + (size_t)(b0 + bl) * (TT * FF) + r * FF;
            p[k] = *reinterpret_cast<const float2*>(base + 10);  // f10, f11
            q[k] = *reinterpret_cast<const float2*>(base + 12);  // f12, f13
        }
    }

    // ---- phase 2: y_j once per (b,j), overlapped with in-flight loads ----
    if (tid < BPB * 4) {
        int bl = tid >> 2;
        int j  = (tid & 3) + 1;
        const float* xl = x + (size_t)(b0 + bl) * (TT * FF) + (size_t)(TT - 1) * FF;
        float w = *wp;
        float d = xl[0];
        for (int k = 1; k < j; k++) d = __fadd_rn(d, xl[k]);  // sequential prefix sum
        float den = __fadd_rn(w, __fmul_rn(xl[4 + j], 25.0f));
        float td  = __fdiv_rn(__fmul_rn(d, 150.0f), den);
        s_y[bl][j - 1] = __fmul_rn(td, 10.0f);
    }

    // ---- phase 3: drain registers into smem ----
#pragma unroll
    for (int k = 0; k < ITERS; k++) {
        int i = tid + k * NT;
        if (i < BPB * SS) {
            int bl = i / SS, r = i - bl * SS;
            s_feat[bl][r][0] = p[k].x;   // f10
            s_feat[bl][r][1] = p[k].y;   // f11
            s_feat[bl][r][2] = q[k].x;   // f12
            s_feat[bl][r][3] = q[k].y;   // f13
        }
    }
    __syncthreads();

    // ---- gather into registers; mask ORed over this block's 4 b's ----
    const int  s    = tid;            // one step per thread
    const bool owns = (s < SS);

    float4   vals[BPB];
    unsigned msk = 0u;

    if (owns) {
        float sf = (float)s;
#pragma unroll
        for (int bl = 0; bl < BPB; bl++) {
            int r0 = min(max((int)__fsub_rn(sf, s_y[bl][0]), 0), SS - 1);
            int r1 = min(max((int)__fsub_rn(sf, s_y[bl][1]), 0), SS - 1);
            int r2 = min(max((int)__fsub_rn(sf, s_y[bl][2]), 0), SS - 1);
            int r3 = min(max((int)__fsub_rn(sf, s_y[bl][3]), 0), SS - 1);
            float4 o;
            o.x = s_feat[bl][r0][0];
            o.y = s_feat[bl][r1][1];
            o.z = s_feat[bl][r2][2];
            o.w = s_feat[bl][r3][3];
            vals[bl] = o;
            msk |= (o.x != 0.0f ? 1u : 0u) | (o.y != 0.0f ? 2u : 0u) |
                   (o.z != 0.0f ? 4u : 0u) | (o.w != 0.0f ? 8u : 0u);
        }
        if (msk) atomicOr(&g_state.mask[s], msk);   // <=1 REDG per (block, step)
    }

    // ---- grid barrier (256 arrivals, all blocks co-resident at occ 2) ----
    __threadfence();
    __syncthreads();
    if (tid == 0) {
        atomicAdd(&g_state.arrive, 1u);
        volatile unsigned* av = &g_state.arrive;
        while (*av < (unsigned)GRID) { __nanosleep(32); }
        __threadfence();
    }
    __syncthreads();

    // ---- emit from registers (stores coalesced in s) ----
    if (owns) {
        unsigned mm = __ldcg(&g_state.mask[s]);
        int sel = mm ? (__ffs(mm) - 1) : -1;
#pragma unroll
        for (int bl = 0; bl < BPB; bl++) {
            float4 o = vals[bl];
            float r = 0.0f;
            r = (sel == 0) ? o.x : r;
            r = (sel == 1) ? o.y : r;
            r = (sel == 2) ? o.z : r;
            r = (sel == 3) ? o.w : r;
            out[(size_t)(b0 + bl) * SS + s] = r;
        }
    }
}

extern "C" void kernel_launch(void* const* d_in, const int* in_sizes, int n_in,
                              void* d_out, int out_size) {
    // metadata order: vi(0), delta_y(1), v_previous(2), x_input(3), w(4)
    const float* x = (const float*)d_in[3];
    const float* w = (const float*)d_in[4];
    float* out = (float*)d_out;

    void* statep = nullptr;
    cudaGetSymbolAddress(&statep, g_state);
    cudaMemsetAsync(statep, 0, sizeof(SyncState));   // graph memset node

    k_all<<<GRID, NT>>>(x, w, out);
}

// round 14
// speedup vs baseline: 1.3351x; 1.3351x over previous
#include <cuda_runtime.h>
#include <cstdint>

#define BB 1024
#define TT 2048
#define FF 16
#define SS 300    // FORWARD_STEPS
#define BPB 7     // batch elements per block
#define GRID 147  // ceil(1024/7); occ 1 -> all blocks co-resident (best frame: R9/R12)
#define NT 320    // >= SS: one thread per step
#define NCHUNK (BPB * SS * 2)   // 4200 16B chunks per block (2 per row)
#define ITERS 14  // ceil(4200/320)

// Cross-block state, zeroed by a memset node before each kernel replay.
struct SyncState {
    unsigned mask[SS];   // 4-bit validity per step (bit j-1 = any temp_j != 0 over all b)
    unsigned arrive;     // grid-barrier arrival counter
};
__device__ SyncState g_state;

// ---------------------------------------------------------------------------
// Single persistent kernel, 147 blocks x 320 threads, 1 CTA/SM.
// Block k owns batches [k*7, k*7+nb). Thread t (< 300) owns step t.
//
// CHUNK-COALESCED staging: thread i loads the i-th 16B chunk (row = i>>1,
// half = i&1, addr = row*64B + 32 + half*16). A warp then touches 16
// consecutive rows = 8 cache lines -> 8 L1tex wavefronts per LDG.128
// instead of 16 (the old row-per-thread pattern), halving the staging
// wavefront floor (~2100 -> ~1050 wf/block) at identical DRAM traffic.
// All loads are front-batched into registers (MLP), y_j computed while they
// fly, then drained to smem.
//
// Bit-exactness: identical _rn op sequences; y_j >= 0 -> SS-1 clamp == TT-1
// clamp (rel_err 0.0 on every passing round since R2).
// ---------------------------------------------------------------------------
__global__ void __launch_bounds__(NT, 1)
k_all(const float* __restrict__ x, const float* __restrict__ wp,
      float* __restrict__ out) {
    const int tid = threadIdx.x;
    const int b0  = blockIdx.x * BPB;
    const int nb  = min(BPB, BB - b0);
    const int nchunk = nb * SS * 2;

    __shared__ float s_feat[BPB][SS][5];  // features 10..13 (+pad; 5 coprime 32 banks)
    __shared__ float s_y[BPB][4];

    // ---- phase 1: front-batch ALL chunk loads into registers ----
    float4 ch[ITERS];
#pragma unroll
    for (int k = 0; k < ITERS; k++) {
        int i = tid + k * NT;
        if (i < nchunk) {
            int rg   = i >> 1;            // global row index within block (0..nb*300-1)
            int half = i & 1;             // 0: f8..f11, 1: f12..f15
            int bl = rg / SS, r = rg - bl * SS;
            const float* base = x + (size_t)(b0 + bl) * (TT * FF) + r * FF;
            ch[k] = *reinterpret_cast<const float4*>(base + 8 + half * 4);
        }
    }

    // ---- phase 2: y_j once per (b,j), overlapped with in-flight loads ----
    if (tid < nb * 4) {
        int bl = tid >> 2;
        int j  = (tid & 3) + 1;
        const float* xl = x + (size_t)(b0 + bl) * (TT * FF) + (size_t)(TT - 1) * FF;
        float w = *wp;
        float d = xl[0];
        for (int k = 1; k < j; k++) d = __fadd_rn(d, xl[k]);  // sequential prefix sum
        float den = __fadd_rn(w, __fmul_rn(xl[4 + j], 25.0f));
        float td  = __fdiv_rn(__fmul_rn(d, 150.0f), den);
        s_y[bl][j - 1] = __fmul_rn(td, 10.0f);
    }

    // ---- phase 3: drain registers into smem (2 useful floats per chunk) ----
#pragma unroll
    for (int k = 0; k < ITERS; k++) {
        int i = tid + k * NT;
        if (i < nchunk) {
            int rg   = i >> 1;
            int half = i & 1;
            int bl = rg / SS, r = rg - bl * SS;
            if (half == 0) {
                s_feat[bl][r][0] = ch[k].z;   // f10
                s_feat[bl][r][1] = ch[k].w;   // f11
            } else {
                s_feat[bl][r][2] = ch[k].x;   // f12
                s_feat[bl][r][3] = ch[k].y;   // f13
            }
        }
    }
    __syncthreads();

    // ---- gather into registers; mask ORed over this block's b's ----
    const int  s    = tid;            // one step per thread; NT >= SS covers all
    const bool owns = (s < SS);

    float4   vals[BPB];
    unsigned msk = 0u;

    if (owns) {
        float sf = (float)s;
#pragma unroll
        for (int bl = 0; bl < BPB; bl++) {
            if (bl >= nb) break;
            int r0 = min(max((int)__fsub_rn(sf, s_y[bl][0]), 0), SS - 1);
            int r1 = min(max((int)__fsub_rn(sf, s_y[bl][1]), 0), SS - 1);
            int r2 = min(max((int)__fsub_rn(sf, s_y[bl][2]), 0), SS - 1);
            int r3 = min(max((int)__fsub_rn(sf, s_y[bl][3]), 0), SS - 1);
            float4 o;
            o.x = s_feat[bl][r0][0];
            o.y = s_feat[bl][r1][1];
            o.z = s_feat[bl][r2][2];
            o.w = s_feat[bl][r3][3];
            vals[bl] = o;
            msk |= (o.x != 0.0f ? 1u : 0u) | (o.y != 0.0f ? 2u : 0u) |
                   (o.z != 0.0f ? 4u : 0u) | (o.w != 0.0f ? 8u : 0u);
        }
        if (msk) atomicOr(&g_state.mask[s], msk);   // <=1 REDG per (block, step)
    }

    // ---- grid barrier (147 arrivals, all blocks co-resident at occ 1) ----
    __threadfence();
    __syncthreads();
    if (tid == 0) {
        atomicAdd(&g_state.arrive, 1u);
        volatile unsigned* av = &g_state.arrive;
        while (*av < (unsigned)GRID) { __nanosleep(32); }
        __threadfence();
    }
    __syncthreads();

    // ---- emit from registers (stores coalesced in s) ----
    if (owns) {
        unsigned mm = __ldcg(&g_state.mask[s]);
        int sel = mm ? (__ffs(mm) - 1) : -1;
#pragma unroll
        for (int bl = 0; bl < BPB; bl++) {
            if (bl >= nb) break;
            float4 o = vals[bl];
            float r = 0.0f;
            r = (sel == 0) ? o.x : r;
            r = (sel == 1) ? o.y : r;
            r = (sel == 2) ? o.z : r;
            r = (sel == 3) ? o.w : r;
            out[(size_t)(b0 + bl) * SS + s] = r;
        }
    }
}

extern "C" void kernel_launch(void* const* d_in, const int* in_sizes, int n_in,
                              void* d_out, int out_size) {
    // metadata order: vi(0), delta_y(1), v_previous(2), x_input(3), w(4)
    const float* x = (const float*)d_in[3];
    const float* w = (const float*)d_in[4];
    float* out = (float*)d_out;

    void* statep = nullptr;
    cudaGetSymbolAddress(&statep, g_state);
    cudaMemsetAsync(statep, 0, sizeof(SyncState));   // graph memset node

    k_all<<<GRID, NT>>>(x, w, out);
}